// round 3
// baseline (speedup 1.0000x reference)
#include <cuda_runtime.h>

// Problem constants (fixed shapes)
#define DD    2048      // hidden dim
#define NTOK  16384     // B*T = 4*4096
#define NE    18        // 16 expert rows + 2 group rows
#define THRV  0.15f

// Global scratch for the expert histogram (no cudaMalloc allowed)
__device__ int g_counts[16];

// Packed dual-fp32 FMA (Blackwell f32x2 pipe; ptxas never auto-fuses this)
__device__ __forceinline__ float2 ffma2(float2 a, float2 b, float2 c) {
    unsigned long long au = *reinterpret_cast<unsigned long long*>(&a);
    unsigned long long bu = *reinterpret_cast<unsigned long long*>(&b);
    unsigned long long cu = *reinterpret_cast<unsigned long long*>(&c);
    unsigned long long du;
    asm("fma.rn.f32x2 %0, %1, %2, %3;" : "=l"(du) : "l"(au), "l"(bu), "l"(cu));
    return *reinterpret_cast<float2*>(&du);
}

__global__ void egr_zero_counts() {
    if (threadIdx.x < 16) g_counts[threadIdx.x] = 0;
}

// One warp handles 2 tokens. Lanes partition D. 256 threads = 16 tokens/block.
__global__ void __launch_bounds__(256) egr_router_kernel(
    const float* __restrict__ x,
    const float* __restrict__ We,    // [16, D]
    const float* __restrict__ Wg,    // [2, D]
    float* __restrict__ out)
{
    __shared__ int hist[16];
    const int tid  = threadIdx.x;
    if (tid < 16) hist[tid] = 0;
    __syncthreads();

    const int warp = tid >> 5;
    const int lane = tid & 31;
    const int tok0 = blockIdx.x * 16 + warp * 2;   // this warp: tok0, tok0+1

    const float4* xA = reinterpret_cast<const float4*>(x + (size_t)tok0 * DD);
    const float4* xB = reinterpret_cast<const float4*>(x + (size_t)(tok0 + 1) * DD);

    float2 accA[NE], accB[NE];
    #pragma unroll
    for (int e = 0; e < NE; e++) {
        accA[e] = make_float2(0.f, 0.f);
        accB[e] = make_float2(0.f, 0.f);
    }

    // D = 2048 floats = 512 float4; 32 lanes -> 16 iterations
    #pragma unroll 2
    for (int k = 0; k < 16; k++) {
        const int q = k * 32 + lane;               // float4 index within row
        float4 xa = __ldcs(xA + q);                // streaming: don't pollute L1
        float4 xb = __ldcs(xB + q);
        float2 xa0 = make_float2(xa.x, xa.y), xa1 = make_float2(xa.z, xa.w);
        float2 xb0 = make_float2(xb.x, xb.y), xb1 = make_float2(xb.z, xb.w);

        #pragma unroll
        for (int e = 0; e < NE; e++) {
            const float4* wp = (e < 16)
                ? reinterpret_cast<const float4*>(We + e * DD)
                : reinterpret_cast<const float4*>(Wg + (e - 16) * DD);
            float4 w = __ldg(wp + q);              // L1-resident (144 KB total)
            float2 w0 = make_float2(w.x, w.y), w1 = make_float2(w.z, w.w);
            accA[e] = ffma2(xa0, w0, accA[e]);
            accA[e] = ffma2(xa1, w1, accA[e]);
            accB[e] = ffma2(xb0, w0, accB[e]);
            accB[e] = ffma2(xb1, w1, accB[e]);
        }
    }

    // Warp all-reduce of 36 partial dots (butterfly -> every lane has full sum)
    float redA[NE], redB[NE];
    #pragma unroll
    for (int e = 0; e < NE; e++) {
        float vA = accA[e].x + accA[e].y;
        float vB = accB[e].x + accB[e].y;
        #pragma unroll
        for (int off = 16; off; off >>= 1) {
            vA += __shfl_xor_sync(0xffffffffu, vA, off);
            vB += __shfl_xor_sync(0xffffffffu, vB, off);
        }
        redA[e] = vA; redB[e] = vB;
    }

    // Lanes 0 and 1 do the routing for token A / token B respectively
    if (lane < 2) {
        float s[NE];
        #pragma unroll
        for (int e = 0; e < NE; e++) s[e] = (lane == 0) ? redA[e] : redB[e];
        const int tok = tok0 + lane;

        const float g0 = 1.f / (1.f + expf(-s[16]));
        const float g1 = 1.f / (1.f + expf(-s[17]));

        // --- Group A: experts 0..7, top-1 softmax prob ---
        float ma = s[0]; int ai = 0;
        #pragma unroll
        for (int j = 1; j < 8; j++) if (s[j] > ma) { ma = s[j]; ai = j; }
        float dena = 0.f;
        #pragma unroll
        for (int j = 0; j < 8; j++) dena += expf(s[j] - ma);
        const float aw = 1.f / dena;               // exp(0)/den

        // --- Group B: experts 8..11 ---
        float mb = s[8]; int bi = 0;
        #pragma unroll
        for (int j = 1; j < 4; j++) if (s[8 + j] > mb) { mb = s[8 + j]; bi = j; }
        float denb = 0.f;
        #pragma unroll
        for (int j = 0; j < 4; j++) denb += expf(s[8 + j] - mb);
        const float bact = (g0 > THRV) ? 1.f : 0.f;
        const float bw = (1.f / denb) * g0 * bact;

        // --- Group C: experts 12..15, top-2 (first-occurrence tie-break) ---
        float b1 = s[12]; int i1 = 0;
        float b2 = -3.402823466e+38f; int i2 = 0;
        #pragma unroll
        for (int j = 1; j < 4; j++) {
            float v = s[12 + j];
            if (v > b1)      { b2 = b1; i2 = i1; b1 = v; i1 = j; }
            else if (v > b2) { b2 = v;  i2 = j; }
        }
        float denc = 0.f;
        #pragma unroll
        for (int j = 0; j < 4; j++) denc += expf(s[12 + j] - b1);
        const float cact = (g1 > THRV) ? 1.f : 0.f;
        const float cg   = g1 * cact;
        const float cw0  = (1.f / denc) * cg;
        const float cw1  = (expf(b2 - b1) / denc) * cg;

        // --- Normalize & write ---
        const float inv = 1.f / (aw + bw + cw0 + cw1 + 1e-8f);
        float* ow = out + (size_t)tok * 6;
        ow[0] = aw  * inv;
        ow[1] = bw  * inv;
        ow[2] = cw0 * inv;
        ow[3] = cw1 * inv;
        ow[4] = 0.f;
        ow[5] = 0.f;

        float* oi = out + (size_t)NTOK * 6 + (size_t)tok * 6;
        oi[0] = (float)ai;
        oi[1] = (float)(8 + bi);
        oi[2] = (float)(12 + i1);
        oi[3] = (float)(12 + i2);
        oi[4] = 0.f;
        oi[5] = 0.f;

        atomicAdd(&hist[ai],      1);
        atomicAdd(&hist[8 + bi],  1);
        atomicAdd(&hist[12 + i1], 1);
        atomicAdd(&hist[12 + i2], 1);
    }

    __syncthreads();
    if (tid < 16) atomicAdd(&g_counts[tid], hist[tid]);
}

__global__ void egr_aux_kernel(float* __restrict__ out) {
    if (threadIdx.x == 0 && blockIdx.x == 0) {
        const float total = 6.0f * (float)NTOK;   // counts.sum(): 6 slots/token
        const float u  = 1.0f / 16.0f;
        const float lu = logf(u);
        float aux = 0.f;
        #pragma unroll
        for (int e = 0; e < 16; e++) {
            // two zero-pads per token land in bin 0 of jnp.bincount
            float c = (float)g_counts[e] + (e == 0 ? 2.0f * (float)NTOK : 0.0f);
            float actual = c / total;
            aux += u * (lu - logf(actual));
        }
        out[(size_t)2 * NTOK * 6] = aux * 0.01f;
    }
}

extern "C" void kernel_launch(void* const* d_in, const int* in_sizes, int n_in,
                              void* d_out, int out_size) {
    const float* x  = (const float*)d_in[0];   // (4,4096,2048) f32
    const float* We = (const float*)d_in[1];   // (16,2048) f32
    const float* Wg = (const float*)d_in[2];   // (2,2048) f32
    float* out = (float*)d_out;                // weights | indices | aux

    egr_zero_counts<<<1, 32>>>();
    egr_router_kernel<<<NTOK / 16, 256>>>(x, We, Wg, out);
    egr_aux_kernel<<<1, 32>>>(out);
}

// round 4
// speedup vs baseline: 1.3380x; 1.3380x over previous
#include <cuda_runtime.h>

// Problem constants (fixed shapes)
#define DD    2048      // hidden dim
#define NTOK  16384     // B*T = 4*4096
#define NE    18        // 16 expert rows + 2 group rows
#define THRV  0.15f
#define ROWQ  (DD / 4)  // 512 ulonglong2 (16B units) per row

// Global scratch for the expert histogram (no cudaMalloc allowed).
// Zero at module load; egr_aux_kernel resets it to zero after each use,
// so every kernel_launch call sees counts==0 -> deterministic & graph-safe.
__device__ int g_counts[16];

// Packed dual-fp32 FMA, operands kept as u64 the whole time (no float2
// marshaling -> no MOV-pair overhead in SASS).
__device__ __forceinline__ unsigned long long ffma2u(
    unsigned long long a, unsigned long long b, unsigned long long c) {
    unsigned long long d;
    asm("fma.rn.f32x2 %0, %1, %2, %3;" : "=l"(d) : "l"(a), "l"(b), "l"(c));
    return d;
}

__device__ __forceinline__ float pairsum(unsigned long long v) {
    float2 f = *reinterpret_cast<float2*>(&v);
    return f.x + f.y;
}

// One warp handles 2 tokens. Lanes partition D. 256 threads = 16 tokens/block.
__global__ void __launch_bounds__(256, 2) egr_router_kernel(
    const float* __restrict__ x,
    const float* __restrict__ We,    // [16, D]
    const float* __restrict__ Wg,    // [2, D]
    float* __restrict__ out)
{
    __shared__ int hist[16];
    const int tid = threadIdx.x;
    if (tid < 16) hist[tid] = 0;
    __syncthreads();

    const int warp = tid >> 5;
    const int lane = tid & 31;
    const int tok0 = blockIdx.x * 16 + warp * 2;   // this warp: tok0, tok0+1

    const ulonglong2* xA  = reinterpret_cast<const ulonglong2*>(x + (size_t)tok0 * DD);
    const ulonglong2* xB  = reinterpret_cast<const ulonglong2*>(x + (size_t)(tok0 + 1) * DD);
    const ulonglong2* Weu = reinterpret_cast<const ulonglong2*>(We);
    const ulonglong2* Wgu = reinterpret_cast<const ulonglong2*>(Wg);

    unsigned long long accA[NE], accB[NE];
    #pragma unroll
    for (int e = 0; e < NE; e++) { accA[e] = 0ull; accB[e] = 0ull; }

    // D = 512 ulonglong2; 32 lanes -> 16 steps; unroll-2 body batches 4 DRAM
    // loads up front (MLP_p1 = 4) so 4 warps/SMSP fully hide 577-cyc latency.
    #pragma unroll 1
    for (int k = 0; k < 16; k += 2) {
        const int qa = (k << 5) + lane;            // 16B-granule index
        const int qb = qa + 32;
        ulonglong2 xa0 = __ldcs(xA + qa);          // streaming: keep W in L1
        ulonglong2 xb0 = __ldcs(xB + qa);
        ulonglong2 xa1 = __ldcs(xA + qb);
        ulonglong2 xb1 = __ldcs(xB + qb);

        #pragma unroll
        for (int e = 0; e < NE; e++) {
            // e is compile-time under full unroll -> ternary resolves statically
            const ulonglong2* wr = (e < 16) ? (Weu + ((size_t)e << 9))
                                            : (Wgu + ((size_t)(e - 16) << 9));
            ulonglong2 w0 = __ldg(wr + qa);
            accA[e] = ffma2u(xa0.x, w0.x, accA[e]);
            accA[e] = ffma2u(xa0.y, w0.y, accA[e]);
            accB[e] = ffma2u(xb0.x, w0.x, accB[e]);
            accB[e] = ffma2u(xb0.y, w0.y, accB[e]);
            ulonglong2 w1 = __ldg(wr + qb);
            accA[e] = ffma2u(xa1.x, w1.x, accA[e]);
            accA[e] = ffma2u(xa1.y, w1.y, accA[e]);
            accB[e] = ffma2u(xb1.x, w1.x, accB[e]);
            accB[e] = ffma2u(xb1.y, w1.y, accB[e]);
        }
    }

    // Warp all-reduce of 36 partial dots (butterfly -> every lane has full sum)
    float redA[NE], redB[NE];
    #pragma unroll
    for (int e = 0; e < NE; e++) {
        float vA = pairsum(accA[e]);
        float vB = pairsum(accB[e]);
        #pragma unroll
        for (int off = 16; off; off >>= 1) {
            vA += __shfl_xor_sync(0xffffffffu, vA, off);
            vB += __shfl_xor_sync(0xffffffffu, vB, off);
        }
        redA[e] = vA; redB[e] = vB;
    }

    // Lanes 0 and 1 do the routing for token A / token B respectively
    if (lane < 2) {
        float s[NE];
        #pragma unroll
        for (int e = 0; e < NE; e++) s[e] = (lane == 0) ? redA[e] : redB[e];
        const int tok = tok0 + lane;

        const float g0 = 1.f / (1.f + expf(-s[16]));
        const float g1 = 1.f / (1.f + expf(-s[17]));

        // --- Group A: experts 0..7, top-1 softmax prob ---
        float ma = s[0]; int ai = 0;
        #pragma unroll
        for (int j = 1; j < 8; j++) if (s[j] > ma) { ma = s[j]; ai = j; }
        float dena = 0.f;
        #pragma unroll
        for (int j = 0; j < 8; j++) dena += expf(s[j] - ma);
        const float aw = 1.f / dena;               // exp(0)/den

        // --- Group B: experts 8..11 ---
        float mb = s[8]; int bi = 0;
        #pragma unroll
        for (int j = 1; j < 4; j++) if (s[8 + j] > mb) { mb = s[8 + j]; bi = j; }
        float denb = 0.f;
        #pragma unroll
        for (int j = 0; j < 4; j++) denb += expf(s[8 + j] - mb);
        const float bact = (g0 > THRV) ? 1.f : 0.f;
        const float bw = (1.f / denb) * g0 * bact;

        // --- Group C: experts 12..15, top-2 (first-occurrence tie-break) ---
        float b1 = s[12]; int i1 = 0;
        float b2 = -3.402823466e+38f; int i2 = 0;
        #pragma unroll
        for (int j = 1; j < 4; j++) {
            float v = s[12 + j];
            if (v > b1)      { b2 = b1; i2 = i1; b1 = v; i1 = j; }
            else if (v > b2) { b2 = v;  i2 = j; }
        }
        float denc = 0.f;
        #pragma unroll
        for (int j = 0; j < 4; j++) denc += expf(s[12 + j] - b1);
        const float cact = (g1 > THRV) ? 1.f : 0.f;
        const float cg   = g1 * cact;
        const float cw0  = (1.f / denc) * cg;
        const float cw1  = (expf(b2 - b1) / denc) * cg;

        // --- Normalize & write ---
        const float inv = 1.f / (aw + bw + cw0 + cw1 + 1e-8f);
        float* ow = out + (size_t)tok * 6;
        ow[0] = aw  * inv;
        ow[1] = bw  * inv;
        ow[2] = cw0 * inv;
        ow[3] = cw1 * inv;
        ow[4] = 0.f;
        ow[5] = 0.f;

        float* oi = out + (size_t)NTOK * 6 + (size_t)tok * 6;
        oi[0] = (float)ai;
        oi[1] = (float)(8 + bi);
        oi[2] = (float)(12 + i1);
        oi[3] = (float)(12 + i2);
        oi[4] = 0.f;
        oi[5] = 0.f;

        atomicAdd(&hist[ai],      1);
        atomicAdd(&hist[8 + bi],  1);
        atomicAdd(&hist[12 + i1], 1);
        atomicAdd(&hist[12 + i2], 1);
    }

    __syncthreads();
    if (tid < 16) atomicAdd(&g_counts[tid], hist[tid]);
}

__global__ void egr_aux_kernel(float* __restrict__ out) {
    if (threadIdx.x == 0 && blockIdx.x == 0) {
        const float total = 6.0f * (float)NTOK;   // counts.sum(): 6 slots/token
        const float u  = 1.0f / 16.0f;
        const float lu = logf(u);
        float aux = 0.f;
        #pragma unroll
        for (int e = 0; e < 16; e++) {
            // two zero-pads per token land in bin 0 of jnp.bincount
            float c = (float)g_counts[e] + (e == 0 ? 2.0f * (float)NTOK : 0.0f);
            float actual = c / total;
            aux += u * (lu - logf(actual));
            g_counts[e] = 0;                      // reset for next replay
        }
        out[(size_t)2 * NTOK * 6] = aux * 0.01f;
    }
}

extern "C" void kernel_launch(void* const* d_in, const int* in_sizes, int n_in,
                              void* d_out, int out_size) {
    const float* x  = (const float*)d_in[0];   // (4,4096,2048) f32
    const float* We = (const float*)d_in[1];   // (16,2048) f32
    const float* Wg = (const float*)d_in[2];   // (2,2048) f32
    float* out = (float*)d_out;                // weights | indices | aux

    egr_router_kernel<<<NTOK / 16, 256>>>(x, We, Wg, out);
    egr_aux_kernel<<<1, 32>>>(out);
}